// round 10
// baseline (speedup 1.0000x reference)
#include <cuda_runtime.h>
#include <cstdint>

// GINEdgeLayer, fused two-layer MLPs on legacy tf32 mma.sync (m16n8k8).
// out = MLP2((1+eps)*H + segment_sum(MLP1([H[src], edge_attr]), dst))
//
// R9: one 512-thread CTA = TWO independent 64-row half-tiles, each with its
// own smem region and its own named barrier (bar.sync 1/2, 256). Barrier and
// latency stalls in one half are covered by the other half's warps.
//
// Launch order (ncu capture = index 3 = fused edge kernel):
//   0: init_agg   1: cvt_msg   2: cvt_self   3: fused_edge   4: fused_node

static constexpr int N_NODES  = 20000;
static constexpr int N_EDGES  = 200000;
static constexpr int DIM      = 128;
static constexpr int EDGE_DIM = 64;
static constexpr int HID      = 256;

// ---- scratch (__device__ globals; no runtime allocation allowed) ----
__device__ float g_agg[(size_t)N_NODES * DIM];
__device__ __align__(16) float g_W1p[2 * 6 * 128 * 36];  // [nh][kc][col][36] tf32
__device__ __align__(16) float g_W2p[8 * 128 * 36];      // [kc][col][36]
__device__ __align__(16) float g_W3p[2 * 4 * 128 * 36];  // [nh][kc][col][36]
__device__ __align__(16) float g_W4p[8 * 128 * 36];      // [kc][col][36]

static inline int cdiv(int a, int b) { return (a + b - 1) / b; }

__device__ __forceinline__ uint32_t smem_u32(const void* p) {
    uint32_t a;
    asm("{ .reg .u64 t; cvta.to.shared.u64 t, %1; cvt.u32.u64 %0, t; }" : "=r"(a) : "l"(p));
    return a;
}
__device__ __forceinline__ uint32_t f2tf32(float f) {
    uint32_t r; asm("cvt.rna.tf32.f32 %0, %1;" : "=r"(r) : "f"(f)); return r;
}
__device__ __forceinline__ int kperm(int w) {        // w in [0,32)
    return (w & 3) * 8 + ((w >> 3) & 3) * 2 + ((w >> 2) & 1);
}

__global__ __launch_bounds__(256)
void init_agg_kernel(const float* __restrict__ H, const float* __restrict__ eps) {
    int i = blockIdx.x * 256 + threadIdx.x;
    if (i < N_NODES * DIM) g_agg[i] = (1.0f + eps[0]) * H[i];
}

// W[K,N] row-major -> P[(chunk*128 + col)*36 + pos], chunk = (n>>7)*(K/32) + (k>>5)
__device__ __forceinline__ void perm_write(const float* __restrict__ W,
                                           float* __restrict__ P,
                                           int K, int N, int idx) {
    int k = idx / N, n = idx - k * N;
    int chunk = (n >> 7) * (K >> 5) + (k >> 5);
    int col = n & 127;
    int pos = kperm(k & 31);
    P[(size_t)(chunk * 128 + col) * 36 + pos] = __uint_as_float(f2tf32(W[idx]));
}

__global__ __launch_bounds__(256)
void cvt_perm2_kernel(const float* __restrict__ Wa, float* __restrict__ Pa, int Ka, int Na,
                      const float* __restrict__ Wb, float* __restrict__ Pb, int Kb, int Nb) {
    int i = blockIdx.x * 256 + threadIdx.x;
    int na = Ka * Na;
    if (i < na)                perm_write(Wa, Pa, Ka, Na, i);
    else if (i < na + Kb * Nb) perm_write(Wb, Pb, Kb, Nb, i - na);
}

// =====================================================================
// Fused 2-layer MLP. One 512-thread CTA = two independent 64-row tiles
// ("halves"), each with 8 warps (2M x 4N, warp tile 32x32) and a private
// named barrier. Per half:
//   stage 1: X1 = relu(rowsA @ W1 + b1)   [64, 256] in SMEM (tf32, permuted)
//   stage 2: Y  = X1 @ W2 + b2            [64, 128]
// EDGE: rowsA[m] = concat(H[src[m]], edge_attr[m]) (K1=192); Y scattered
//       via red.global.add into Cout[dst[m]].  !EDGE: rowsA = Ain (K1=128).
// =====================================================================
template<int K1, bool EDGE>
__global__ void __launch_bounds__(512, 1)
fused_mlp(const float* __restrict__ Ain,
          const float* __restrict__ W1p, const float* __restrict__ b1,
          const float* __restrict__ W2p, const float* __restrict__ b2,
          float*       __restrict__ Cout,
          const int*   __restrict__ srcv, const int* __restrict__ dstv,
          const float* __restrict__ H,   const float* __restrict__ EA,
          int M)
{
    constexpr int NK1 = K1 / 32;
    constexpr int NK2 = HID / 32;           // 8
    constexpr int AST = 36;                 // A smem row stride (floats)
    constexpr int BST = 36;                 // B smem col stride (floats)
    constexpr int XST = 260;                // X1 row stride (260 % 32 == 4)
    constexpr int ABYTES = 64 * AST * 4;    // 9216 (single-buffered)
    constexpr int BBYTES = 128 * BST * 4;   // 18432
    constexpr int BCHUNK16 = BBYTES / 16;   // 1152 16-byte pieces
    constexpr int OFF_A = 1024;
    constexpr int OFF_B = OFF_A + ABYTES;           // 10240
    constexpr int OFF_X = OFF_B + 2 * BBYTES;       // 47104
    constexpr int HALF  = OFF_X + 64 * XST * 4;     // 113664 per half
    static_assert((NK1 & 1) == 0, "stage-2 prefetch assumes even NK1");

    extern __shared__ char smem_raw[];
    const int tid = threadIdx.x;
    const int h   = tid >> 8;          // half 0/1
    const int lt  = tid & 255;         // thread within half
    char* smem = smem_raw + (size_t)h * HALF;

    int*   srcIdx = (int*)smem;                 // 64 ints
    int*   dstIdx = (int*)(smem + 256);         // 64 ints
    float* As  = (float*)(smem + OFF_A);
    float* Bs0 = (float*)(smem + OFF_B);
    float* Bs1 = (float*)(smem + OFF_B + BBYTES);
    float* X1  = (float*)(smem + OFF_X);

    const int wid_h = lt >> 5, lane = lt & 31;
    const int g  = lane >> 2, t = lane & 3;
    const int wm = wid_h & 1, wn = wid_h >> 1;       // 2M x 4N warp grid
    const int tile = blockIdx.x * 2 + h;
    const int m0   = tile * 64;
    const int barid = 1 + h;

#define HBAR() asm volatile("bar.sync %0, 256;" :: "r"(barid) : "memory")

    if (EDGE && lt < 64) {
        int gm = m0 + lt;
        int cm = gm < M ? gm : M - 1;
        srcIdx[lt] = srcv[cm];
        dstIdx[lt] = dstv[cm];
    }
    HBAR();

    // ---- A staging: thread (row=lt/4, aq=lt&3) handles 8 consecutive k ----
    const int ar = lt >> 2, aq = lt & 3;
    int agm = m0 + ar; if (agm >= M) agm = M - 1;

    auto lda = [&](int kc, float4* v) {
        int k0 = kc * 32 + aq * 8;
        const float* s;
        if (EDGE) {
            s = (k0 < DIM) ? H + (size_t)srcIdx[ar] * DIM + k0
                           : EA + (size_t)agm * EDGE_DIM + (k0 - DIM);
        } else {
            s = Ain + (size_t)agm * K1 + k0;
        }
        v[0] = *reinterpret_cast<const float4*>(s);
        v[1] = *reinterpret_cast<const float4*>(s + 4);
    };
    // permuted store: pairs (j, j+4) land at adjacent pos -> STS.64
    auto sta = [&](const float4* v) {
        const float f[8] = { v[0].x, v[0].y, v[0].z, v[0].w,
                             v[1].x, v[1].y, v[1].z, v[1].w };
        float* d = As + ar * AST + aq * 2;
#pragma unroll
        for (int j = 0; j < 4; j++) {
            uint2 u; u.x = f2tf32(f[j]); u.y = f2tf32(f[j + 4]);
            *reinterpret_cast<uint2*>(d + j * 8) = u;
        }
    };

    // ---- B staging: flat cp.async copy of one pre-permuted 18432-B chunk ----
    auto ldb = [&](const float* srcChunk, float* buf) {
        uint32_t d = smem_u32(buf);
        const char* s = (const char*)srcChunk;
#pragma unroll
        for (int i = 0; i < 5; i++) {
            int idx = lt + i * 256;
            if (idx < BCHUNK16)
                asm volatile("cp.async.cg.shared.global [%0], [%1], 16;"
                             :: "r"(d + idx * 16), "l"(s + (size_t)idx * 16) : "memory");
        }
        asm volatile("cp.async.commit_group;" ::: "memory");
    };

    float acc[2][4][4];
    float4 av[2];

    // fragment compute core: A from abase (stride ast), B from Bcur
    auto mma_chunk = [&](const float* abase, int ast, const float* Bcur) {
        float a[2][2][8];                         // [mi][lo/hi][8]
#pragma unroll
        for (int mi = 0; mi < 2; mi++)
#pragma unroll
            for (int lh = 0; lh < 2; lh++) {
                const float* ap = abase + (mi * 16 + lh * 8) * ast;
                *reinterpret_cast<float4*>(&a[mi][lh][0]) =
                    *reinterpret_cast<const float4*>(ap);
                *reinterpret_cast<float4*>(&a[mi][lh][4]) =
                    *reinterpret_cast<const float4*>(ap + 4);
            }
#pragma unroll
        for (int ni = 0; ni < 4; ni++) {
            const float* bp = Bcur + (wn * 32 + ni * 8 + g) * BST + t * 8;
            float b[8];
            *reinterpret_cast<float4*>(&b[0]) = *reinterpret_cast<const float4*>(bp);
            *reinterpret_cast<float4*>(&b[4]) = *reinterpret_cast<const float4*>(bp + 4);
#pragma unroll
            for (int kk = 0; kk < 4; kk++) {
                uint32_t b0 = __float_as_uint(b[2 * kk]);
                uint32_t b1 = __float_as_uint(b[2 * kk + 1]);
#pragma unroll
                for (int mi = 0; mi < 2; mi++) {
                    asm volatile(
                        "mma.sync.aligned.m16n8k8.row.col.f32.tf32.tf32.f32 "
                        "{%0,%1,%2,%3}, {%4,%5,%6,%7}, {%8,%9}, {%0,%1,%2,%3};"
                        : "+f"(acc[mi][ni][0]), "+f"(acc[mi][ni][1]),
                          "+f"(acc[mi][ni][2]), "+f"(acc[mi][ni][3])
                        : "r"(__float_as_uint(a[mi][0][2 * kk])),
                          "r"(__float_as_uint(a[mi][1][2 * kk])),
                          "r"(__float_as_uint(a[mi][0][2 * kk + 1])),
                          "r"(__float_as_uint(a[mi][1][2 * kk + 1])),
                          "r"(b0), "r"(b1));
                }
            }
        }
    };

    // ================= stage 1: two N-halves of 128 =================
#pragma unroll 1
    for (int nh = 0; nh < 2; nh++) {
#pragma unroll
        for (int mi = 0; mi < 2; mi++)
#pragma unroll
            for (int ni = 0; ni < 4; ni++)
#pragma unroll
                for (int r = 0; r < 4; r++) acc[mi][ni][r] = 0.0f;

        ldb(W1p + (size_t)(nh * NK1) * 128 * 36, Bs0);
        lda(0, av);
        sta(av);
        asm volatile("cp.async.wait_group 0;" ::: "memory");
        HBAR();

#pragma unroll 1
        for (int kc = 0; kc < NK1; kc++) {
            const int p = kc & 1;
            float* Bcur = p ? Bs1 : Bs0;
            float* Bnxt = p ? Bs0 : Bs1;

            if (kc + 1 < NK1) {
                ldb(W1p + (size_t)(nh * NK1 + kc + 1) * 128 * 36, Bnxt);
                lda(kc + 1, av);
            }

            mma_chunk(As + (wm * 32 + g) * AST + t * 8, AST, Bcur);

            HBAR();                         // all warps done reading As
            if (kc + 1 < NK1) {
                sta(av);                    // overwrite single A buffer
                asm volatile("cp.async.wait_group 0;" ::: "memory");
            }
            HBAR();                         // publish As + B(k+1)
        }

        // stage-2 chunk-0 prefetch into the free Bs0 (NK1 even -> last Bcur = Bs1)
        if (nh == 1) ldb(W2p, Bs0);

        // epilogue: bias + relu, tf32-convert, permuted store into X1 smem
        float2 bv[4];
#pragma unroll
        for (int ni = 0; ni < 4; ni++)
            bv[ni] = *reinterpret_cast<const float2*>(b1 + nh * 128 + wn * 32 + ni * 8 + 2 * t);

        const int t2 = 2 * t, t3 = 2 * t + 1;
        const int posx = (t2 & 3) * 8 + (t2 >> 2);   // + ni*2
        const int posy = (t3 & 3) * 8 + (t3 >> 2);
#pragma unroll
        for (int mi = 0; mi < 2; mi++)
#pragma unroll
            for (int half = 0; half < 2; half++) {
                const int row = wm * 32 + mi * 16 + g + half * 8;
                float* xp = X1 + (size_t)row * XST + (nh * 4 + wn) * 32;
#pragma unroll
                for (int ni = 0; ni < 4; ni++) {
                    float x = fmaxf(acc[mi][ni][half * 2 + 0] + bv[ni].x, 0.0f);
                    float y = fmaxf(acc[mi][ni][half * 2 + 1] + bv[ni].y, 0.0f);
                    xp[posx + ni * 2] = __uint_as_float(f2tf32(x));
                    xp[posy + ni * 2] = __uint_as_float(f2tf32(y));
                }
            }
    }

    // ================= stage 2: Y = X1 @ W2 + b2 (K = 256) =================
#pragma unroll
    for (int mi = 0; mi < 2; mi++)
#pragma unroll
        for (int ni = 0; ni < 4; ni++)
#pragma unroll
            for (int r = 0; r < 4; r++) acc[mi][ni][r] = 0.0f;

    asm volatile("cp.async.wait_group 0;" ::: "memory");
    HBAR();                                 // publishes X1 to this half's warps

#pragma unroll 1
    for (int kc = 0; kc < NK2; kc++) {
        const int p = kc & 1;
        float* Bcur = p ? Bs1 : Bs0;
        float* Bnxt = p ? Bs0 : Bs1;

        if (kc + 1 < NK2) ldb(W2p + (size_t)(kc + 1) * 128 * 36, Bnxt);

        mma_chunk(X1 + (size_t)(wm * 32 + g) * XST + kc * 32 + t * 8, XST, Bcur);

        if (kc + 1 < NK2)
            asm volatile("cp.async.wait_group 0;" ::: "memory");
        HBAR();
    }

    // ---- stage-2 epilogue ----
    float2 bv[4];
#pragma unroll
    for (int ni = 0; ni < 4; ni++)
        bv[ni] = *reinterpret_cast<const float2*>(b2 + wn * 32 + ni * 8 + 2 * t);

#pragma unroll
    for (int mi = 0; mi < 2; mi++)
#pragma unroll
        for (int half = 0; half < 2; half++) {
            const int row_l = wm * 32 + mi * 16 + g + half * 8;
            const int gm = m0 + row_l;
            if (gm < M) {
                const size_t orow = EDGE ? (size_t)dstIdx[row_l] : (size_t)gm;
                float* cp = Cout + orow * DIM + wn * 32 + 2 * t;
#pragma unroll
                for (int ni = 0; ni < 4; ni++) {
                    float x = acc[mi][ni][half * 2 + 0] + bv[ni].x;
                    float y = acc[mi][ni][half * 2 + 1] + bv[ni].y;
                    if (EDGE) {
                        asm volatile("red.global.add.v2.f32 [%0], {%1, %2};"
                                     :: "l"(cp + ni * 8), "f"(x), "f"(y) : "memory");
                    } else {
                        *reinterpret_cast<float2*>(cp + ni * 8) = make_float2(x, y);
                    }
                }
            }
        }
#undef HBAR
}

// ===================== launch =====================
extern "C" void kernel_launch(void* const* d_in, const int* in_sizes, int n_in,
                              void* d_out, int out_size)
{
    const float* H         = (const float*)d_in[0];
    const int*   edge_idx  = (const int*)  d_in[1];
    const float* edge_attr = (const float*)d_in[2];
    const float* eps       = (const float*)d_in[3];
    const float* msg_W1    = (const float*)d_in[4];
    const float* msg_b1    = (const float*)d_in[5];
    const float* msg_W2    = (const float*)d_in[6];
    const float* msg_b2    = (const float*)d_in[7];
    const float* self_W1   = (const float*)d_in[8];
    const float* self_b1   = (const float*)d_in[9];
    const float* self_W2   = (const float*)d_in[10];
    const float* self_b2   = (const float*)d_in[11];

    const int* src = edge_idx;
    const int* dst = edge_idx + N_EDGES;
    float* out = (float*)d_out;

    float *agg, *W1p, *W2p, *W3p, *W4p;
    cudaGetSymbolAddress((void**)&agg, g_agg);
    cudaGetSymbolAddress((void**)&W1p, g_W1p);
    cudaGetSymbolAddress((void**)&W2p, g_W2p);
    cudaGetSymbolAddress((void**)&W3p, g_W3p);
    cudaGetSymbolAddress((void**)&W4p, g_W4p);

    constexpr int K1 = DIM + EDGE_DIM;  // 192
    // per half: 1024 + 9216 (A) + 2*18432 (B) + 64*260*4 (X1) = 113664
    constexpr int SMEM = 2 * 113664;    // 227328

    cudaFuncSetAttribute((const void*)fused_mlp<K1, true>,
                         cudaFuncAttributeMaxDynamicSharedMemorySize, SMEM);
    cudaFuncSetAttribute((const void*)fused_mlp<DIM, false>,
                         cudaFuncAttributeMaxDynamicSharedMemorySize, SMEM);

    // 0) agg = (1+eps)*H
    init_agg_kernel<<<cdiv(N_NODES * DIM, 256), 256>>>(H, eps);
    // 1) msg weights -> permuted tf32
    cvt_perm2_kernel<<<cdiv(K1 * HID + HID * DIM, 256), 256>>>(
        msg_W1, W1p, K1, HID, msg_W2, W2p, HID, DIM);
    // 2) self weights -> permuted tf32
    cvt_perm2_kernel<<<cdiv(DIM * HID + HID * DIM, 256), 256>>>(
        self_W1, W3p, DIM, HID, self_W2, W4p, HID, DIM);

    // 3) fused edge MLP + scatter into agg   (ncu capture target: launch idx 3)
    // 3125 64-row tiles, 2 tiles per CTA
    fused_mlp<K1, true><<<cdiv(cdiv(N_EDGES, 64), 2), 512, SMEM>>>(
        nullptr, W1p, msg_b1, W2p, msg_b2, agg, src, dst, H, edge_attr, N_EDGES);

    // 4) fused node MLP -> out  (313 tiles, 2 per CTA)
    fused_mlp<DIM, false><<<cdiv(cdiv(N_NODES, 64), 2), 512, SMEM>>>(
        agg, W3p, self_b1, W4p, self_b2, out, nullptr, nullptr, nullptr, nullptr, N_NODES);
}

// round 11
// speedup vs baseline: 1.2461x; 1.2461x over previous
#include <cuda_runtime.h>
#include <cstdint>

// GINEdgeLayer via split-GEMM reformulation on legacy tf32 mma.sync.
//   concat(H[src], EA) @ W1 == H[src]@W1a + EA@W1b
//   P = H@W1a + b1 computed per-NODE once (1.3 GFLOP) instead of per-edge
//   (13.1 GFLOP). Edge kernel: X1 = relu(P[src] + EA@W1b), K=64.
// Total FLOPs 35.4G -> 23.6G.
//
// Launch order (ncu capture = index 3 = fused edge kernel):
//   0: init_agg   1: cvt_all   2: P-gemm (MODE 0)   3: edge (MODE 1)   4: node (MODE 2)

static constexpr int N_NODES  = 20000;
static constexpr int N_EDGES  = 200000;
static constexpr int DIM      = 128;
static constexpr int EDGE_DIM = 64;
static constexpr int HID      = 256;

// ---- scratch (__device__ globals; no runtime allocation allowed) ----
__device__ float g_agg[(size_t)N_NODES * DIM];
__device__ __align__(16) float g_P[(size_t)N_NODES * HID];   // 20.5 MB, L2-resident
__device__ __align__(16) float g_W1ap[8 * 128 * 36];  // [2nh*4kc][col][36] tf32 permuted
__device__ __align__(16) float g_W1bp[4 * 128 * 36];  // [2nh*2kc][col][36]
__device__ __align__(16) float g_W2p [8 * 128 * 36];  // [8kc][col][36]
__device__ __align__(16) float g_W3p [8 * 128 * 36];  // [2nh*4kc][col][36]
__device__ __align__(16) float g_W4p [8 * 128 * 36];  // [8kc][col][36]

static inline int cdiv(int a, int b) { return (a + b - 1) / b; }

__device__ __forceinline__ uint32_t smem_u32(const void* p) {
    uint32_t a;
    asm("{ .reg .u64 t; cvta.to.shared.u64 t, %1; cvt.u32.u64 %0, t; }" : "=r"(a) : "l"(p));
    return a;
}
__device__ __forceinline__ uint32_t f2tf32(float f) {
    uint32_t r; asm("cvt.rna.tf32.f32 %0, %1;" : "=r"(r) : "f"(f)); return r;
}
__device__ __forceinline__ int kperm(int w) {        // bijection on 0..31
    return (w & 3) * 8 + ((w >> 3) & 3) * 2 + ((w >> 2) & 1);
}

__global__ __launch_bounds__(256)
void init_agg_kernel(const float* __restrict__ H, const float* __restrict__ eps) {
    int i = blockIdx.x * 256 + threadIdx.x;
    if (i < N_NODES * DIM) g_agg[i] = (1.0f + eps[0]) * H[i];
}

// W[K,N] row-major -> P[(chunk*128 + col)*36 + pos], chunk = (n>>7)*(K/32) + (k>>5)
__device__ __forceinline__ void perm_write(const float* __restrict__ W,
                                           float* __restrict__ P,
                                           int K, int N, int idx) {
    int k = idx / N, n = idx - k * N;
    int chunk = (n >> 7) * (K >> 5) + (k >> 5);
    int col = n & 127;
    int pos = kperm(k & 31);
    P[(size_t)(chunk * 128 + col) * 36 + pos] = __uint_as_float(f2tf32(W[idx]));
}

// All five weight matrices in one launch.
__global__ __launch_bounds__(256)
void cvt_all_kernel(const float* __restrict__ mW1, const float* __restrict__ mW2,
                    const float* __restrict__ sW1, const float* __restrict__ sW2,
                    float* __restrict__ W1ap, float* __restrict__ W1bp,
                    float* __restrict__ W2p,  float* __restrict__ W3p,
                    float* __restrict__ W4p) {
    int i = blockIdx.x * 256 + threadIdx.x;
    // mW1 [192,256]: rows 0..127 -> W1a (K=128), rows 128..191 -> W1b (K=64)
    if (i < 32768)        perm_write(mW1, W1ap, 128, 256, i);          // source idx == i
    else if (i < 49152) { // W1b: source element mW1[i] with local idx i-32768
        int l = i - 32768;
        int k = l >> 8, n = l & 255;
        int chunk = (n >> 7) * 2 + (k >> 5);
        W1bp[(size_t)(chunk * 128 + (n & 127)) * 36 + kperm(k & 31)] =
            __uint_as_float(f2tf32(mW1[i]));
    }
    else if (i < 81920)   perm_write(mW2, W2p, 256, 128, i - 49152);
    else if (i < 114688)  perm_write(sW1, W3p, 128, 256, i - 81920);
    else if (i < 147456)  perm_write(sW2, W4p, 256, 128, i - 114688);
}

// =====================================================================
// Unified kernel, CTA tile = 128 rows, 512 threads (16 warps, 4M x 4N).
// MODE 0 (P):    P = Ain(H)@W1a + b1            K1=128, stage-1 only, fp32 out [.,256]
// MODE 1 (EDGE): X1 = relu(P[src] + EA@W1b)     K1=64, A upfront; stage 2 scatters
//                Y  = X1@W2 + b2  -> red.global.add into Cout[dst]
// MODE 2 (NODE): X1 = relu(Ain@W3 + b3); Y = X1@W4 + b4 -> Cout rows
// =====================================================================
template<int MODE>
__global__ void __launch_bounds__(512, 1)
fused_mlp(const float* __restrict__ Ain,
          const float* __restrict__ W1p, const float* __restrict__ b1,
          const float* __restrict__ W2p, const float* __restrict__ b2,
          const float* __restrict__ Pg,
          float*       __restrict__ Cout,
          const int*   __restrict__ srcv, const int* __restrict__ dstv,
          int M)
{
    constexpr bool EDGE = (MODE == 1);
    constexpr int  K1   = EDGE ? 64 : 128;
    constexpr int  NK1  = K1 / 32;           // 2 or 4
    constexpr int  NK2  = HID / 32;          // 8
    constexpr int  AST = 36, BST = 36, XST = 260;
    constexpr int  CHUNKB = 128 * 36 * 4;    // 18432 B per operand chunk
    constexpr int  BCHUNK16 = CHUNKB / 16;   // 1152
    constexpr int  OFF_A = 1024;
    constexpr int  OFF_B = OFF_A + 2 * CHUNKB;    // 37888
    constexpr int  OFF_X = OFF_B + 2 * CHUNKB;    // 74752

    extern __shared__ char smem[];
    int*   srcIdx = (int*)smem;
    int*   dstIdx = (int*)(smem + 512);
    float* As0 = (float*)(smem + OFF_A);
    float* As1 = (float*)(smem + OFF_A + CHUNKB);
    float* Bs0 = (float*)(smem + OFF_B);
    float* Bs1 = (float*)(smem + OFF_B + CHUNKB);
    float* X1  = (float*)(smem + OFF_X);

    const int tid  = threadIdx.x;
    const int lane = tid & 31;
    const int g    = lane >> 2, t = lane & 3;
    const int wid  = tid >> 5;
    const int wm   = wid & 3, wn = wid >> 2;      // 4M x 4N warp grid
    const int m0   = blockIdx.x * 128;

    if (EDGE && tid < 128) {
        int gm = m0 + tid;
        int cm = gm < M ? gm : M - 1;
        srcIdx[tid] = srcv[cm];
        dstIdx[tid] = dstv[cm];
    }
    if (EDGE) __syncthreads();

    // ---- A staging helpers: thread (row=tid/4, aq=tid&3), 8 consecutive k ----
    const int ar = tid >> 2, aq = tid & 3;
    int agm = m0 + ar; if (agm >= M) agm = M - 1;

    auto lda = [&](int kc, float4* v) {          // streamed modes (0,2)
        const float* s = Ain + (size_t)agm * K1 + kc * 32 + aq * 8;
        v[0] = *reinterpret_cast<const float4*>(s);
        v[1] = *reinterpret_cast<const float4*>(s + 4);
    };
    auto sta = [&](float* buf, const float4* v) {  // permuted STS.64 pairs
        const float f[8] = { v[0].x, v[0].y, v[0].z, v[0].w,
                             v[1].x, v[1].y, v[1].z, v[1].w };
        float* d = buf + ar * AST + aq * 2;
#pragma unroll
        for (int j = 0; j < 4; j++) {
            uint2 u; u.x = f2tf32(f[j]); u.y = f2tf32(f[j + 4]);
            *reinterpret_cast<uint2*>(d + j * 8) = u;
        }
    };

    // ---- B staging: flat cp.async copy of one pre-permuted 18432-B chunk ----
    auto ldb = [&](const float* srcChunk, float* buf) {
        uint32_t d = smem_u32(buf);
        const char* s = (const char*)srcChunk;
#pragma unroll
        for (int i = 0; i < 3; i++) {
            int idx = tid + i * 512;
            if (idx < BCHUNK16)
                asm volatile("cp.async.cg.shared.global [%0], [%1], 16;"
                             :: "r"(d + idx * 16), "l"(s + (size_t)idx * 16) : "memory");
        }
        asm volatile("cp.async.commit_group;" ::: "memory");
    };

    float acc[2][4][4];
    auto zacc = [&]() {
#pragma unroll
        for (int mi = 0; mi < 2; mi++)
#pragma unroll
            for (int ni = 0; ni < 4; ni++)
#pragma unroll
                for (int r = 0; r < 4; r++) acc[mi][ni][r] = 0.0f;
    };

    // fragment compute core: A from abase (stride ast), B from Bcur
    auto mma_chunk = [&](const float* abase, int ast, const float* Bcur) {
        float a[2][2][8];
#pragma unroll
        for (int mi = 0; mi < 2; mi++)
#pragma unroll
            for (int lh = 0; lh < 2; lh++) {
                const float* ap = abase + (mi * 16 + lh * 8) * ast;
                *reinterpret_cast<float4*>(&a[mi][lh][0]) =
                    *reinterpret_cast<const float4*>(ap);
                *reinterpret_cast<float4*>(&a[mi][lh][4]) =
                    *reinterpret_cast<const float4*>(ap + 4);
            }
#pragma unroll
        for (int ni = 0; ni < 4; ni++) {
            const float* bp = Bcur + (wn * 32 + ni * 8 + g) * BST + t * 8;
            float b[8];
            *reinterpret_cast<float4*>(&b[0]) = *reinterpret_cast<const float4*>(bp);
            *reinterpret_cast<float4*>(&b[4]) = *reinterpret_cast<const float4*>(bp + 4);
#pragma unroll
            for (int kk = 0; kk < 4; kk++) {
                uint32_t b0 = __float_as_uint(b[2 * kk]);
                uint32_t b1r = __float_as_uint(b[2 * kk + 1]);
#pragma unroll
                for (int mi = 0; mi < 2; mi++) {
                    asm volatile(
                        "mma.sync.aligned.m16n8k8.row.col.f32.tf32.tf32.f32 "
                        "{%0,%1,%2,%3}, {%4,%5,%6,%7}, {%8,%9}, {%0,%1,%2,%3};"
                        : "+f"(acc[mi][ni][0]), "+f"(acc[mi][ni][1]),
                          "+f"(acc[mi][ni][2]), "+f"(acc[mi][ni][3])
                        : "r"(__float_as_uint(a[mi][0][2 * kk])),
                          "r"(__float_as_uint(a[mi][1][2 * kk])),
                          "r"(__float_as_uint(a[mi][0][2 * kk + 1])),
                          "r"(__float_as_uint(a[mi][1][2 * kk + 1])),
                          "r"(b0), "r"(b1r));
                }
            }
        }
    };

    // ---- stage-1 epilogue (per N-half) ----
    auto epilogue1 = [&](int nh) {
        if constexpr (MODE == 0) {               // P = acc + b1, fp32 to gmem [., 256]
            float2 bv[4];
#pragma unroll
            for (int ni = 0; ni < 4; ni++)
                bv[ni] = *reinterpret_cast<const float2*>(b1 + nh * 128 + wn * 32 + ni * 8 + 2 * t);
#pragma unroll
            for (int mi = 0; mi < 2; mi++)
#pragma unroll
                for (int half = 0; half < 2; half++) {
                    const int row_l = wm * 32 + mi * 16 + g + half * 8;
                    const int gm = m0 + row_l;
                    if (gm < M) {
                        float* cp = Cout + (size_t)gm * HID + nh * 128 + wn * 32 + 2 * t;
#pragma unroll
                        for (int ni = 0; ni < 4; ni++)
                            *reinterpret_cast<float2*>(cp + ni * 8) =
                                make_float2(acc[mi][ni][half * 2 + 0] + bv[ni].x,
                                            acc[mi][ni][half * 2 + 1] + bv[ni].y);
                    }
                }
        } else {                                  // relu(add + acc) -> X1 (permuted tf32)
            float2 bv[4];
            if (!EDGE) {
#pragma unroll
                for (int ni = 0; ni < 4; ni++)
                    bv[ni] = *reinterpret_cast<const float2*>(b1 + nh * 128 + wn * 32 + ni * 8 + 2 * t);
            }
            const int t2 = 2 * t, t3 = 2 * t + 1;
            const int posx = (t2 & 3) * 8 + (t2 >> 2);
            const int posy = (t3 & 3) * 8 + (t3 >> 2);
#pragma unroll
            for (int mi = 0; mi < 2; mi++)
#pragma unroll
                for (int half = 0; half < 2; half++) {
                    const int row_l = wm * 32 + mi * 16 + g + half * 8;
                    float* xp = X1 + (size_t)row_l * XST + (nh * 4 + wn) * 32;
                    const float* pp = nullptr;
                    if (EDGE)
                        pp = Pg + (size_t)srcIdx[row_l] * HID + nh * 128 + wn * 32 + 2 * t;
#pragma unroll
                    for (int ni = 0; ni < 4; ni++) {
                        float ax, ay;
                        if (EDGE) {
                            float2 pv = *reinterpret_cast<const float2*>(pp + ni * 8);
                            ax = pv.x; ay = pv.y;
                        } else { ax = bv[ni].x; ay = bv[ni].y; }
                        float x = fmaxf(acc[mi][ni][half * 2 + 0] + ax, 0.0f);
                        float y = fmaxf(acc[mi][ni][half * 2 + 1] + ay, 0.0f);
                        xp[posx + ni * 2] = __uint_as_float(f2tf32(x));
                        xp[posy + ni * 2] = __uint_as_float(f2tf32(y));
                    }
                }
        }
    };

    // ================= stage 1 =================
    if constexpr (EDGE) {
        // A (edge_attr) staged upfront: 2 chunks, dense rows of 64 floats
        ldb(W1p, Bs0);                          // chunk (nh0,kc0)
#pragma unroll
        for (int kc = 0; kc < 2; kc++) {
            const float* s = Ain + (size_t)agm * EDGE_DIM + kc * 32 + aq * 8;
            float4 v[2];
            v[0] = *reinterpret_cast<const float4*>(s);
            v[1] = *reinterpret_cast<const float4*>(s + 4);
            sta(kc ? As1 : As0, v);
        }
        zacc();
        asm volatile("cp.async.wait_group 0;" ::: "memory");
        __syncthreads();

#pragma unroll
        for (int c = 0; c < 4; c++) {           // (nh,kc) = c>>1, c&1
            const float* nxt = (c < 3) ? W1p + (size_t)(c + 1) * 128 * 36
                                       : W2p;   // prefetch W2 chunk 0
            float* Bcur = (c & 1) ? Bs1 : Bs0;
            float* Bnxt = (c & 1) ? Bs0 : Bs1;
            ldb(nxt, Bnxt);
            mma_chunk(((c & 1) ? As1 : As0) + (wm * 32 + g) * AST + t * 8, AST, Bcur);
            asm volatile("cp.async.wait_group 0;" ::: "memory");
            __syncthreads();
            if (c == 1) { epilogue1(0); zacc(); }
            else if (c == 3) { epilogue1(1); }
        }
        __syncthreads();                        // publish X1 (W2 chunk 0 already waited)
    } else {
        float4 av[2];
#pragma unroll 1
        for (int nh = 0; nh < 2; nh++) {
            zacc();
            ldb(W1p + (size_t)(nh * NK1) * 128 * 36, Bs0);
            lda(0, av);
            sta(As0, av);
            asm volatile("cp.async.wait_group 0;" ::: "memory");
            __syncthreads();

#pragma unroll 1
            for (int kc = 0; kc < NK1; kc++) {
                const int p = kc & 1;
                float* Acur = p ? As1 : As0;
                float* Bcur = p ? Bs1 : Bs0;
                float* Anxt = p ? As0 : As1;
                float* Bnxt = p ? Bs0 : Bs1;
                if (kc + 1 < NK1) {
                    ldb(W1p + (size_t)(nh * NK1 + kc + 1) * 128 * 36, Bnxt);
                    lda(kc + 1, av);
                }
                mma_chunk(Acur + (wm * 32 + g) * AST + t * 8, AST, Bcur);
                if (kc + 1 < NK1) {
                    sta(Anxt, av);
                    asm volatile("cp.async.wait_group 0;" ::: "memory");
                }
                __syncthreads();
            }
            if (MODE == 2 && nh == 1) ldb(W2p, Bs0);   // NK1=4 even -> Bs0 free
            epilogue1(nh);
        }
        if constexpr (MODE == 0) return;        // P-GEMM: stage-1 only
        asm volatile("cp.async.wait_group 0;" ::: "memory");
        __syncthreads();                        // publish X1 + W2 chunk 0
    }

    // ================= stage 2: Y = X1 @ W2 + b2 (K = 256) =================
    if constexpr (MODE != 0) {
        zacc();
#pragma unroll 1
        for (int kc = 0; kc < NK2; kc++) {
            const int p = kc & 1;
            float* Bcur = p ? Bs1 : Bs0;
            float* Bnxt = p ? Bs0 : Bs1;
            if (kc + 1 < NK2) ldb(W2p + (size_t)(kc + 1) * 128 * 36, Bnxt);
            mma_chunk(X1 + (size_t)(wm * 32 + g) * XST + kc * 32 + t * 8, XST, Bcur);
            if (kc + 1 < NK2)
                asm volatile("cp.async.wait_group 0;" ::: "memory");
            __syncthreads();
        }

        float2 bv[4];
#pragma unroll
        for (int ni = 0; ni < 4; ni++)
            bv[ni] = *reinterpret_cast<const float2*>(b2 + wn * 32 + ni * 8 + 2 * t);

#pragma unroll
        for (int mi = 0; mi < 2; mi++)
#pragma unroll
            for (int half = 0; half < 2; half++) {
                const int row_l = wm * 32 + mi * 16 + g + half * 8;
                const int gm = m0 + row_l;
                if (gm < M) {
                    const size_t orow = EDGE ? (size_t)dstIdx[row_l] : (size_t)gm;
                    float* cp = Cout + orow * DIM + wn * 32 + 2 * t;
#pragma unroll
                    for (int ni = 0; ni < 4; ni++) {
                        float x = acc[mi][ni][half * 2 + 0] + bv[ni].x;
                        float y = acc[mi][ni][half * 2 + 1] + bv[ni].y;
                        if (EDGE) {
                            asm volatile("red.global.add.v2.f32 [%0], {%1, %2};"
                                         :: "l"(cp + ni * 8), "f"(x), "f"(y) : "memory");
                        } else {
                            *reinterpret_cast<float2*>(cp + ni * 8) = make_float2(x, y);
                        }
                    }
                }
            }
    }
}

// ===================== launch =====================
extern "C" void kernel_launch(void* const* d_in, const int* in_sizes, int n_in,
                              void* d_out, int out_size)
{
    const float* H         = (const float*)d_in[0];
    const int*   edge_idx  = (const int*)  d_in[1];
    const float* edge_attr = (const float*)d_in[2];
    const float* eps       = (const float*)d_in[3];
    const float* msg_W1    = (const float*)d_in[4];
    const float* msg_b1    = (const float*)d_in[5];
    const float* msg_W2    = (const float*)d_in[6];
    const float* msg_b2    = (const float*)d_in[7];
    const float* self_W1   = (const float*)d_in[8];
    const float* self_b1   = (const float*)d_in[9];
    const float* self_W2   = (const float*)d_in[10];
    const float* self_b2   = (const float*)d_in[11];

    const int* src = edge_idx;
    const int* dst = edge_idx + N_EDGES;
    float* out = (float*)d_out;

    float *agg, *P, *W1ap, *W1bp, *W2p, *W3p, *W4p;
    cudaGetSymbolAddress((void**)&agg,  g_agg);
    cudaGetSymbolAddress((void**)&P,    g_P);
    cudaGetSymbolAddress((void**)&W1ap, g_W1ap);
    cudaGetSymbolAddress((void**)&W1bp, g_W1bp);
    cudaGetSymbolAddress((void**)&W2p,  g_W2p);
    cudaGetSymbolAddress((void**)&W3p,  g_W3p);
    cudaGetSymbolAddress((void**)&W4p,  g_W4p);

    constexpr int SMEM_P  = 1024 + 4 * 18432;                   //  74752 (no X1)
    constexpr int SMEM_F  = 1024 + 4 * 18432 + 128 * 260 * 4;   // 207872

    cudaFuncSetAttribute((const void*)fused_mlp<0>,
                         cudaFuncAttributeMaxDynamicSharedMemorySize, SMEM_P);
    cudaFuncSetAttribute((const void*)fused_mlp<1>,
                         cudaFuncAttributeMaxDynamicSharedMemorySize, SMEM_F);
    cudaFuncSetAttribute((const void*)fused_mlp<2>,
                         cudaFuncAttributeMaxDynamicSharedMemorySize, SMEM_F);

    // 0) agg = (1+eps)*H
    init_agg_kernel<<<cdiv(N_NODES * DIM, 256), 256>>>(H, eps);
    // 1) all weights -> permuted tf32 (W1 split into W1a/W1b)
    cvt_all_kernel<<<cdiv(147456, 256), 256>>>(msg_W1, msg_W2, self_W1, self_W2,
                                               W1ap, W1bp, W2p, W3p, W4p);
    // 2) P = H @ W1a + b1   [N, 256]
    fused_mlp<0><<<cdiv(N_NODES, 128), 512, SMEM_P>>>(
        H, W1ap, msg_b1, nullptr, nullptr, nullptr, P, nullptr, nullptr, N_NODES);
    // 3) edge: X1 = relu(P[src] + EA@W1b); agg[dst] += X1@W2 + b2   (ncu idx 3)
    fused_mlp<1><<<cdiv(N_EDGES, 128), 512, SMEM_F>>>(
        edge_attr, W1bp, nullptr, W2p, msg_b2, P, agg, src, dst, N_EDGES);
    // 4) node: out = MLP2(agg)
    fused_mlp<2><<<cdiv(N_NODES, 128), 512, SMEM_F>>>(
        agg, W3p, self_b1, W4p, self_b2, nullptr, out, nullptr, nullptr, N_NODES);
}